// round 2
// baseline (speedup 1.0000x reference)
#include <cuda_runtime.h>
#include <cuda_bf16.h>

// CIN layer: B=1024, F0=32, E=64, K=128 per layer, half-split feeding forward.
//
// Decomposition:
//   hidden_{l+1}[b,j,e] (j<64)  -- dense per-e GEMM with on-the-fly A = x_i * h_j
//   out direct halves:  sum_e cur = <W_k , S[b]>  with S[b,i,j] = sum_e x[b,i,e]*h[b,j,e]
//
// Scratch hidden tensors live in __device__ globals (no allocation).

#define B_SZ   1024
#define F0     32
#define E_SZ   64
#define K_SZ   128
#define HALF   64

__device__ float g_h1[B_SZ * HALF * E_SZ];   // [b][j][e], 16 MB
__device__ float g_h2[B_SZ * HALF * E_SZ];   // [b][j][e], 16 MB

// ---------------------------------------------------------------------------
// Hidden kernel: hout[b][k][e] = bias[k] + sum_{i<32, j<FI} x[b,i,e]*h[b,j,e]*W[(i*FI+j)*128+k]
// for k in [0,64).  M = B*E = 65536 rows, tile BM=128 x BN=64, 128 threads,
// 8x8 register blocking. A-tile never materialized: a = x_i * h_j.
// ---------------------------------------------------------------------------
template<int FI>
__global__ void __launch_bounds__(128)
cin_hidden(const float* __restrict__ x, const float* __restrict__ h,
           const float* __restrict__ W, const float* __restrict__ bias,
           float* __restrict__ hout)
{
    extern __shared__ float sm[];
    float* xs = sm;                         // [128][33]   (m-major, padded)
    float* hs = sm + 128 * 33;              // [128][FI+1] (m-major, padded)
    float* ws = hs + 128 * (FI + 1);        // [FI][68]    (j-major, padded, 16B-aligned rows)

    const int tid = threadIdx.x;
    const int tx  = tid & 7;                // k-group (8 groups x 8 k = 64)
    const int ty  = tid >> 3;               // m-group (16 groups x 8 m = 128)
    const int m0  = blockIdx.x * 128;

    // load x tile: xs[mr][i]
    for (int idx = tid; idx < 128 * 32; idx += 128) {
        int i = idx >> 7, mr = idx & 127;
        int m = m0 + mr, b = m >> 6, e = m & 63;
        xs[mr * 33 + i] = x[(b * 32 + i) * 64 + e];
    }
    // load h tile: hs[mr][j]
    for (int idx = tid; idx < 128 * FI; idx += 128) {
        int j = idx >> 7, mr = idx & 127;
        int m = m0 + mr, b = m >> 6, e = m & 63;
        hs[mr * (FI + 1) + j] = h[(b * FI + j) * 64 + e];
    }

    float acc[8][8];
#pragma unroll
    for (int mm = 0; mm < 8; ++mm)
#pragma unroll
        for (int nn = 0; nn < 8; ++nn) acc[mm][nn] = 0.f;

    for (int i = 0; i < 32; ++i) {
        __syncthreads();  // protects ws reuse (and initial xs/hs load at i=0)
        // stage W chunk for this i: ws[j][k], k<64, vectorized
        for (int idx = tid; idx < FI * 16; idx += 128) {
            int j = idx >> 4, kq = idx & 15;
            float4 w = *reinterpret_cast<const float4*>(W + (i * FI + j) * 128 + kq * 4);
            *reinterpret_cast<float4*>(&ws[j * 68 + kq * 4]) = w;
        }
        __syncthreads();

        float xr[8];
#pragma unroll
        for (int mm = 0; mm < 8; ++mm) xr[mm] = xs[(ty * 8 + mm) * 33 + i];

#pragma unroll 4
        for (int j = 0; j < FI; ++j) {
            float hr[8], wv[8], p[8];
#pragma unroll
            for (int mm = 0; mm < 8; ++mm) hr[mm] = hs[(ty * 8 + mm) * (FI + 1) + j];
#pragma unroll
            for (int nn = 0; nn < 8; ++nn) wv[nn] = ws[j * 68 + tx * 8 + nn];
#pragma unroll
            for (int mm = 0; mm < 8; ++mm) p[mm] = xr[mm] * hr[mm];
#pragma unroll
            for (int mm = 0; mm < 8; ++mm)
#pragma unroll
                for (int nn = 0; nn < 8; ++nn) acc[mm][nn] += p[mm] * wv[nn];
        }
    }

    float bv[8];
#pragma unroll
    for (int nn = 0; nn < 8; ++nn) bv[nn] = bias[tx * 8 + nn];
#pragma unroll
    for (int mm = 0; mm < 8; ++mm) {
        int m = m0 + ty * 8 + mm, b = m >> 6, e = m & 63;
#pragma unroll
        for (int nn = 0; nn < 8; ++nn) {
            int k = tx * 8 + nn;
            hout[(b * HALF + k) * 64 + e] = acc[mm][nn] + bv[nn];
        }
    }
}

// ---------------------------------------------------------------------------
// S + direct kernel: for NB=8 batches per CTA,
//   S[bb][i][j] = sum_e x[b,i,e]*h[b,j,e]        (phase 1, in smem)
//   out[b, outoff+k] = 64*bias[koff+k] + sum_t S[bb][t]*W[t*128+koff+k]  (phase 2)
// ---------------------------------------------------------------------------
template<int FI, int KOUT>
__global__ void __launch_bounds__(256)
cin_sd(const float* __restrict__ x, const float* __restrict__ h,
       const float* __restrict__ W, const float* __restrict__ bias,
       float* __restrict__ out, int koff, int outoff)
{
    constexpr int NB  = 8;
    constexpr int FAN = 32 * FI;
    extern __shared__ float sm[];
    float* xs  = sm;                    // 32*64
    float* hs  = xs + 2048;             // FI*65
    float* Ss  = hs + FI * 65;          // NB * FAN
    float* red = Ss + NB * FAN;         // 256*4

    const int tid = threadIdx.x;
    const int b0  = blockIdx.x * NB;

    // phase 1: per-batch S
    for (int bb = 0; bb < NB; ++bb) {
        int b = b0 + bb;
        __syncthreads();
        for (int idx = tid; idx < 2048; idx += 256) xs[idx] = x[b * 2048 + idx];
        for (int idx = tid; idx < FI * 64; idx += 256) {
            int j = idx >> 6, e = idx & 63;
            hs[j * 65 + e] = h[(b * FI + j) * 64 + e];
        }
        __syncthreads();

        constexpr int TJ = FI / 4;          // j groups of 4
        if (tid < 16 * TJ) {                // 16 i-groups of 2
            int tig = tid / TJ, tjg = tid % TJ;
            float a[2][4] = {{0.f,0.f,0.f,0.f},{0.f,0.f,0.f,0.f}};
            for (int e = 0; e < 64; ++e) {
                float x0 = xs[(tig * 2 + 0) * 64 + e];
                float x1 = xs[(tig * 2 + 1) * 64 + e];
#pragma unroll
                for (int dj = 0; dj < 4; ++dj) {
                    float hv = hs[(tjg * 4 + dj) * 65 + e];
                    a[0][dj] += x0 * hv;
                    a[1][dj] += x1 * hv;
                }
            }
#pragma unroll
            for (int di = 0; di < 2; ++di)
#pragma unroll
                for (int dj = 0; dj < 4; ++dj)
                    Ss[bb * FAN + (tig * 2 + di) * FI + (tjg * 4 + dj)] = a[di][dj];
        }
    }
    __syncthreads();

    // phase 2: out = S . W  (t-split across P parts, float4 W loads)
    constexpr int NKV = KOUT / 4;
    constexpr int P   = 256 / NKV;
    constexpr int TP  = FAN / P;
    const int p  = tid / NKV;
    const int kq = tid % NKV;

    float4 acc[NB];
#pragma unroll
    for (int bb = 0; bb < NB; ++bb) acc[bb] = make_float4(0.f, 0.f, 0.f, 0.f);

    for (int t = p * TP; t < (p + 1) * TP; ++t) {
        float4 w = *reinterpret_cast<const float4*>(W + t * 128 + koff + kq * 4);
#pragma unroll
        for (int bb = 0; bb < NB; ++bb) {
            float s = Ss[bb * FAN + t];
            acc[bb].x += s * w.x;
            acc[bb].y += s * w.y;
            acc[bb].z += s * w.z;
            acc[bb].w += s * w.w;
        }
    }

    for (int bb = 0; bb < NB; ++bb) {
        __syncthreads();
        reinterpret_cast<float4*>(red)[tid] = acc[bb];
        __syncthreads();
        if (tid < KOUT) {
            int k = tid;
            float s = 0.f;
#pragma unroll
            for (int pp = 0; pp < P; ++pp)
                s += red[(pp * NKV + (k >> 2)) * 4 + (k & 3)];
            out[(b0 + bb) * 256 + outoff + k] = s + 64.0f * bias[koff + k];
        }
    }
}

// ---------------------------------------------------------------------------
extern "C" void kernel_launch(void* const* d_in, const int* in_sizes, int n_in,
                              void* d_out, int out_size)
{
    const float* x  = (const float*)d_in[0];
    const float* W0 = (const float*)d_in[1];
    const float* b0 = (const float*)d_in[2];
    const float* W1 = (const float*)d_in[3];
    const float* b1 = (const float*)d_in[4];
    const float* W2 = (const float*)d_in[5];
    const float* b2 = (const float*)d_in[6];
    float* out = (float*)d_out;

    float *h1p, *h2p;
    cudaGetSymbolAddress((void**)&h1p, g_h1);
    cudaGetSymbolAddress((void**)&h2p, g_h2);

    const int smH32 = (128 * 33 + 128 * 33 + 32 * 68) * 4;                   // 42.5 KB
    const int smH64 = (128 * 33 + 128 * 65 + 64 * 68) * 4;                   // 67.6 KB
    const int smS32 = (2048 + 32 * 65 + 8 * 1024 + 1024) * 4;                // 53.4 KB
    const int smS64 = (2048 + 64 * 65 + 8 * 2048 + 1024) * 4;                // 94.5 KB

    cudaFuncSetAttribute(cin_hidden<32>, cudaFuncAttributeMaxDynamicSharedMemorySize, smH32);
    cudaFuncSetAttribute(cin_hidden<64>, cudaFuncAttributeMaxDynamicSharedMemorySize, smH64);
    cudaFuncSetAttribute(cin_sd<32, 64>, cudaFuncAttributeMaxDynamicSharedMemorySize, smS32);
    cudaFuncSetAttribute(cin_sd<64, 64>, cudaFuncAttributeMaxDynamicSharedMemorySize, smS64);
    cudaFuncSetAttribute(cin_sd<64, 128>, cudaFuncAttributeMaxDynamicSharedMemorySize, smS64);

    const int nM = (B_SZ * E_SZ) / 128;   // 512 CTAs

    // hidden chain (dense per-e, lower halves)
    cin_hidden<32><<<nM, 128, smH32>>>(x, x,   W0, b0, h1p);
    cin_hidden<64><<<nM, 128, smH64>>>(x, h1p, W1, b1, h2p);

    // direct halves via S-trick
    cin_sd<32, 64 ><<<B_SZ / 8, 256, smS32>>>(x, x,   W0, b0, out, 64, 0);
    cin_sd<64, 64 ><<<B_SZ / 8, 256, smS64>>>(x, h1p, W1, b1, out, 64, 64);
    cin_sd<64, 128><<<B_SZ / 8, 256, smS64>>>(x, h2p, W2, b2, out, 0, 128);
}

// round 4
// speedup vs baseline: 2.2619x; 2.2619x over previous
#include <cuda_runtime.h>
#include <cuda_bf16.h>
#include <cstdint>

#define B_SZ 1024

__device__ float g_h1[B_SZ * 64 * 64];
__device__ float g_h2[B_SZ * 64 * 64];
// W in fragment-linear order: per 64-K chunk: [s(4)][nfrag(8)][lane(32)] uint4{hi01,hi89,lo01,lo89}
__device__ __align__(16) uint4 g_Wf0[16 * 1024];
__device__ __align__(16) uint4 g_Wf1[32 * 1024];

__device__ __forceinline__ uint32_t smem_u32(const void* p) {
    uint32_t a;
    asm("{ .reg .u64 t; cvta.to.shared.u64 t, %1; cvt.u32.u64 %0, t; }" : "=r"(a) : "l"(p));
    return a;
}
__device__ __forceinline__ uint32_t pack_hi(float a, float b) {
    return __byte_perm(__float_as_uint(a), __float_as_uint(b), 0x7632);
}
__device__ __forceinline__ uint32_t pack_lo(float a, float b) {
    float la = a - __uint_as_float(__float_as_uint(a) & 0xFFFF0000u);
    float lb = b - __uint_as_float(__float_as_uint(b) & 0xFFFF0000u);
    uint32_t r;
    asm("cvt.rn.bf16x2.f32 %0, %1, %2;" : "=r"(r) : "f"(lb), "f"(la));
    return r;
}
__device__ __forceinline__ void mma16816(float* c, uint32_t a0, uint32_t a1,
                                         uint32_t a2, uint32_t a3,
                                         uint32_t b0, uint32_t b1) {
    asm volatile(
        "mma.sync.aligned.m16n8k16.row.col.f32.bf16.bf16.f32 "
        "{%0,%1,%2,%3}, {%4,%5,%6,%7}, {%8,%9}, {%0,%1,%2,%3};"
        : "+f"(c[0]), "+f"(c[1]), "+f"(c[2]), "+f"(c[3])
        : "r"(a0), "r"(a1), "r"(a2), "r"(a3), "r"(b0), "r"(b1));
}

// ---------------------------------------------------------------------------
// W prep: fragment-linear bf16 hi/lo. out[c*1024 + s*256 + f*32 + lane] =
//   {hi(k0,k0+1), hi(k0+8,k0+9), lo(...), lo(...)} for n = f*8 + lane/4,
//   k0 = c*64 + s*16 + (lane&3)*2.  Hidden cols n<64 only.
// ---------------------------------------------------------------------------
__global__ void __launch_bounds__(256)
wfrag(const float* __restrict__ W, uint4* __restrict__ out) {
    const int c = blockIdx.x;
    for (int t = threadIdx.x; t < 1024; t += 256) {
        int s = t >> 8, f = (t >> 5) & 7, lane = t & 31;
        int n = f * 8 + (lane >> 2);
        int k0 = c * 64 + s * 16 + (lane & 3) * 2;
        float w00 = W[(k0    ) * 128 + n], w01 = W[(k0 + 1) * 128 + n];
        float w08 = W[(k0 + 8) * 128 + n], w09 = W[(k0 + 9) * 128 + n];
        uint4 o;
        o.x = pack_hi(w00, w01);
        o.y = pack_hi(w08, w09);
        o.z = pack_lo(w00, w01);
        o.w = pack_lo(w08, w09);
        out[c * 1024 + t] = o;
    }
}

// ---------------------------------------------------------------------------
// Hidden layer via mma.sync: hout[b,n,e] (n<64) = bias[n] + sum_K A*W,
// A[(b,e),(i,j)] = x[b,i,e]*h[b,j,e].  grid=512, block=256 (8 warps = 4m x 2n).
// A frags computed in registers; B frags cp.async double-buffered in SMEM.
// ---------------------------------------------------------------------------
template<int FI>
__global__ void __launch_bounds__(256)
cin_mma(const float* __restrict__ x, const float* __restrict__ h,
        const uint4* __restrict__ Wf, const float* __restrict__ bias,
        float* __restrict__ hout)
{
    constexpr int NC = (32 * FI) / 64;   // 64-K chunks
    constexpr int HP = FI + 2;
    constexpr int OFF_XS = 256;
    constexpr int OFF_HS = OFF_XS + 128 * 33 * 4;
    constexpr int OFF_B  = OFF_HS + 128 * HP * 4;

    extern __shared__ char smem[];
    float* bias_s = (float*)smem;
    float* xs = (float*)(smem + OFF_XS);   // [128][33]
    float* hs = (float*)(smem + OFF_HS);   // [128][HP]
    const uint32_t Bsm = smem_u32(smem) + OFF_B;   // 2 x 16KB

    const int tid  = threadIdx.x;
    const int lane = tid & 31;
    const int wid  = tid >> 5;
    const int wm   = wid & 3, wn = wid >> 2;
    const int q2   = (lane & 3) * 2;
    const int b0   = blockIdx.x * 2;

    if (tid < 64) bias_s[tid] = bias[tid];
    for (int idx = tid; idx < 4096; idx += 256) {
        int i = idx >> 7, mr = idx & 127;
        xs[mr * 33 + i] = x[((b0 + (mr >> 6)) * 32 + i) * 64 + (mr & 63)];
    }
    for (int idx = tid; idx < FI * 128; idx += 256) {
        int j = idx >> 7, mr = idx & 127;
        hs[mr * HP + j] = h[((b0 + (mr >> 6)) * FI + j) * 64 + (mr & 63)];
    }

    // prefetch B chunks 0,1
#pragma unroll
    for (int pc = 0; pc < 2; ++pc) {
#pragma unroll
        for (int r = 0; r < 4; ++r) {
            uint32_t dst = Bsm + pc * 16384u + (uint32_t)(tid + r * 256) * 16u;
            const uint4* src = Wf + pc * 1024 + tid + r * 256;
            asm volatile("cp.async.cg.shared.global [%0], [%1], 16;"
                         :: "r"(dst), "l"(src));
        }
        asm volatile("cp.async.commit_group;");
    }

    float acc[2][4][4];
#pragma unroll
    for (int mf = 0; mf < 2; ++mf)
#pragma unroll
        for (int nf = 0; nf < 4; ++nf)
#pragma unroll
            for (int r = 0; r < 4; ++r) acc[mf][nf][r] = 0.f;

    const int ra_base = wm * 32 + (lane >> 2);

    for (int c = 0; c < NC; ++c) {
        asm volatile("cp.async.wait_group 1;" ::: "memory");
        __syncthreads();
        const uint32_t Bb = Bsm + (uint32_t)(c & 1) * 16384u;

#pragma unroll
        for (int s = 0; s < 4; ++s) {
            // B frags for this warp (4 n8 frags)
            uint4 Bf[4];
#pragma unroll
            for (int nf = 0; nf < 4; ++nf) {
                uint32_t addr = Bb + (uint32_t)(((s * 8) + wn * 4 + nf) * 32 + lane) * 16u;
                asm volatile("ld.shared.v4.u32 {%0,%1,%2,%3}, [%4];"
                             : "=r"(Bf[nf].x), "=r"(Bf[nf].y),
                               "=r"(Bf[nf].z), "=r"(Bf[nf].w)
                             : "r"(addr));
            }
            const int i  = (FI == 64) ? c : (2 * c + (s >> 1));
            const int j0 = ((FI == 64) ? s * 16 : (s & 1) * 16) + q2;

#pragma unroll
            for (int mf = 0; mf < 2; ++mf) {
                const int ra = ra_base + mf * 16;
                const int rb = ra + 8;
                float xa = xs[ra * 33 + i];
                float xb = xs[rb * 33 + i];
                float2 ha0 = *(const float2*)&hs[ra * HP + j0];
                float2 ha8 = *(const float2*)&hs[ra * HP + j0 + 8];
                float2 hb0 = *(const float2*)&hs[rb * HP + j0];
                float2 hb8 = *(const float2*)&hs[rb * HP + j0 + 8];
                float pa0 = xa * ha0.x, pa1 = xa * ha0.y;
                float pa8 = xa * ha8.x, pa9 = xa * ha8.y;
                float pb0 = xb * hb0.x, pb1 = xb * hb0.y;
                float pb8 = xb * hb8.x, pb9 = xb * hb8.y;
                uint32_t ah0 = pack_hi(pa0, pa1), ah1 = pack_hi(pb0, pb1);
                uint32_t ah2 = pack_hi(pa8, pa9), ah3 = pack_hi(pb8, pb9);
                uint32_t al0 = pack_lo(pa0, pa1), al1 = pack_lo(pb0, pb1);
                uint32_t al2 = pack_lo(pa8, pa9), al3 = pack_lo(pb8, pb9);
#pragma unroll
                for (int nf = 0; nf < 4; ++nf) {
                    mma16816(acc[mf][nf], ah0, ah1, ah2, ah3, Bf[nf].x, Bf[nf].y);
                    mma16816(acc[mf][nf], ah0, ah1, ah2, ah3, Bf[nf].z, Bf[nf].w);
                    mma16816(acc[mf][nf], al0, al1, al2, al3, Bf[nf].x, Bf[nf].y);
                }
            }
        }
        __syncthreads();
        if (c + 2 < NC) {
#pragma unroll
            for (int r = 0; r < 4; ++r) {
                uint32_t dst = Bsm + (uint32_t)(c & 1) * 16384u
                             + (uint32_t)(tid + r * 256) * 16u;
                const uint4* src = Wf + (c + 2) * 1024 + tid + r * 256;
                asm volatile("cp.async.cg.shared.global [%0], [%1], 16;"
                             :: "r"(dst), "l"(src));
            }
        }
        asm volatile("cp.async.commit_group;");
    }

    // epilogue: D -> hout[b][n][e] + bias
#pragma unroll
    for (int mf = 0; mf < 2; ++mf) {
        const int ra = ra_base + mf * 16;
        const int bidx = b0 + (ra >> 6);
        const int ea = ra & 63;
        float* basep = hout + (size_t)bidx * 64 * 64;
#pragma unroll
        for (int nf = 0; nf < 4; ++nf) {
            const int n = wn * 32 + nf * 8 + q2;
            float bv0 = bias_s[n], bv1 = bias_s[n + 1];
            basep[n * 64 + ea]           = acc[mf][nf][0] + bv0;
            basep[(n + 1) * 64 + ea]     = acc[mf][nf][1] + bv1;
            basep[n * 64 + ea + 8]       = acc[mf][nf][2] + bv0;
            basep[(n + 1) * 64 + ea + 8] = acc[mf][nf][3] + bv1;
        }
    }
}

// ---------------------------------------------------------------------------
// S + direct kernel (unchanged): direct halves via S[b,i,j]=sum_e x*h.
// ---------------------------------------------------------------------------
template<int FI, int KOUT>
__global__ void __launch_bounds__(256)
cin_sd(const float* __restrict__ x, const float* __restrict__ h,
       const float* __restrict__ W, const float* __restrict__ bias,
       float* __restrict__ out, int koff, int outoff)
{
    constexpr int NB  = 8;
    constexpr int FAN = 32 * FI;
    extern __shared__ float sm[];
    float* xs  = sm;
    float* hs  = xs + 2048;
    float* Ss  = hs + FI * 65;
    float* red = Ss + NB * FAN;

    const int tid = threadIdx.x;
    const int b0  = blockIdx.x * NB;

    for (int bb = 0; bb < NB; ++bb) {
        int b = b0 + bb;
        __syncthreads();
        for (int idx = tid; idx < 2048; idx += 256) xs[idx] = x[b * 2048 + idx];
        for (int idx = tid; idx < FI * 64; idx += 256) {
            int j = idx >> 6, e = idx & 63;
            hs[j * 65 + e] = h[(b * FI + j) * 64 + e];
        }
        __syncthreads();

        constexpr int TJ = FI / 4;
        if (tid < 16 * TJ) {
            int tig = tid / TJ, tjg = tid % TJ;
            float a[2][4] = {{0.f,0.f,0.f,0.f},{0.f,0.f,0.f,0.f}};
            for (int e = 0; e < 64; ++e) {
                float x0 = xs[(tig * 2 + 0) * 64 + e];
                float x1 = xs[(tig * 2 + 1) * 64 + e];
#pragma unroll
                for (int dj = 0; dj < 4; ++dj) {
                    float hv = hs[(tjg * 4 + dj) * 65 + e];
                    a[0][dj] += x0 * hv;
                    a[1][dj] += x1 * hv;
                }
            }
#pragma unroll
            for (int di = 0; di < 2; ++di)
#pragma unroll
                for (int dj = 0; dj < 4; ++dj)
                    Ss[bb * FAN + (tig * 2 + di) * FI + (tjg * 4 + dj)] = a[di][dj];
        }
    }
    __syncthreads();

    constexpr int NKV = KOUT / 4;
    constexpr int P   = 256 / NKV;
    constexpr int TP  = FAN / P;
    const int p  = tid / NKV;
    const int kq = tid % NKV;

    float4 acc[NB];
#pragma unroll
    for (int bb = 0; bb < NB; ++bb) acc[bb] = make_float4(0.f, 0.f, 0.f, 0.f);

    for (int t = p * TP; t < (p + 1) * TP; ++t) {
        float4 w = *reinterpret_cast<const float4*>(W + t * 128 + koff + kq * 4);
#pragma unroll
        for (int bb = 0; bb < NB; ++bb) {
            float s = Ss[bb * FAN + t];
            acc[bb].x += s * w.x; acc[bb].y += s * w.y;
            acc[bb].z += s * w.z; acc[bb].w += s * w.w;
        }
    }

    for (int bb = 0; bb < NB; ++bb) {
        __syncthreads();
        reinterpret_cast<float4*>(red)[tid] = acc[bb];
        __syncthreads();
        if (tid < KOUT) {
            int k = tid;
            float s = 0.f;
#pragma unroll
            for (int pp = 0; pp < P; ++pp)
                s += red[(pp * NKV + (k >> 2)) * 4 + (k & 3)];
            out[(b0 + bb) * 256 + outoff + k] = s + 64.0f * bias[koff + k];
        }
    }
}

// ---------------------------------------------------------------------------
extern "C" void kernel_launch(void* const* d_in, const int* in_sizes, int n_in,
                              void* d_out, int out_size)
{
    const float* x  = (const float*)d_in[0];
    const float* W0 = (const float*)d_in[1];
    const float* b0 = (const float*)d_in[2];
    const float* W1 = (const float*)d_in[3];
    const float* b1 = (const float*)d_in[4];
    const float* W2 = (const float*)d_in[5];
    const float* b2 = (const float*)d_in[6];
    float* out = (float*)d_out;

    float *h1p, *h2p;
    uint4 *wf0, *wf1;
    cudaGetSymbolAddress((void**)&h1p, g_h1);
    cudaGetSymbolAddress((void**)&h2p, g_h2);
    cudaGetSymbolAddress((void**)&wf0, g_Wf0);
    cudaGetSymbolAddress((void**)&wf1, g_Wf1);

    const int smM32 = 256 + 128 * 33 * 4 + 128 * 34 * 4 + 32768;   // 67968
    const int smM64 = 256 + 128 * 33 * 4 + 128 * 66 * 4 + 32768;   // 84352
    const int smS32 = (2048 + 32 * 65 + 8 * 1024 + 1024) * 4;
    const int smS64 = (2048 + 64 * 65 + 8 * 2048 + 1024) * 4;

    cudaFuncSetAttribute(cin_mma<32>, cudaFuncAttributeMaxDynamicSharedMemorySize, smM32);
    cudaFuncSetAttribute(cin_mma<64>, cudaFuncAttributeMaxDynamicSharedMemorySize, smM64);
    cudaFuncSetAttribute(cin_sd<32, 64>,  cudaFuncAttributeMaxDynamicSharedMemorySize, smS32);
    cudaFuncSetAttribute(cin_sd<64, 64>,  cudaFuncAttributeMaxDynamicSharedMemorySize, smS64);
    cudaFuncSetAttribute(cin_sd<64, 128>, cudaFuncAttributeMaxDynamicSharedMemorySize, smS64);

    wfrag<<<16, 256>>>(W0, wf0);
    wfrag<<<32, 256>>>(W1, wf1);

    cin_mma<32><<<512, 256, smM32>>>(x, x,   wf0, b0, h1p);
    cin_mma<64><<<512, 256, smM64>>>(x, h1p, wf1, b1, h2p);

    cin_sd<32, 64 ><<<B_SZ / 8, 256, smS32>>>(x, x,   W0, b0, out, 64, 0);
    cin_sd<64, 64 ><<<B_SZ / 8, 256, smS64>>>(x, h1p, W1, b1, out, 64, 64);
    cin_sd<64, 128><<<B_SZ / 8, 256, smS64>>>(x, h2p, W2, b2, out, 0, 128);
}

// round 5
// speedup vs baseline: 2.7410x; 1.2118x over previous
#include <cuda_runtime.h>
#include <cuda_bf16.h>
#include <cstdint>

#define B_SZ 1024

// hidden activations, [b][e][j] layout (e-major for coalesced float4 fills)
__device__ float g_h1[B_SZ * 64 * 64];
__device__ float g_h2[B_SZ * 64 * 64];
// W fragment-linear: per 64-K chunk: [s(4)][nfrag(8)][lane(32)] uint4{hi01,hi23',lo01,lo23'}
__device__ __align__(16) uint4 g_Wf0[16 * 1024];
__device__ __align__(16) uint4 g_Wf1[32 * 1024];
// S matrices (direct path): S[b][i*FI+j]
__device__ float g_S0[B_SZ * 1024];
__device__ float g_S1[B_SZ * 2048];
__device__ float g_S2[B_SZ * 2048];
// k-split partials: [z(8)][b][256 cols]
__device__ float g_part[8 * B_SZ * 256];

__device__ __forceinline__ uint32_t smem_u32(const void* p) {
    uint32_t a;
    asm("{ .reg .u64 t; cvta.to.shared.u64 t, %1; cvt.u32.u64 %0, t; }" : "=r"(a) : "l"(p));
    return a;
}
__device__ __forceinline__ uint32_t pack_hi(float a, float b) {
    return __byte_perm(__float_as_uint(a), __float_as_uint(b), 0x7632);
}
__device__ __forceinline__ uint32_t pack_lo(float a, float b) {
    float la = a - __uint_as_float(__float_as_uint(a) & 0xFFFF0000u);
    float lb = b - __uint_as_float(__float_as_uint(b) & 0xFFFF0000u);
    uint32_t r;
    asm("cvt.rn.bf16x2.f32 %0, %1, %2;" : "=r"(r) : "f"(lb), "f"(la));
    return r;
}
__device__ __forceinline__ void mma16816(float* c, uint32_t a0, uint32_t a1,
                                         uint32_t a2, uint32_t a3,
                                         uint32_t b0, uint32_t b1) {
    asm volatile(
        "mma.sync.aligned.m16n8k16.row.col.f32.bf16.bf16.f32 "
        "{%0,%1,%2,%3}, {%4,%5,%6,%7}, {%8,%9}, {%0,%1,%2,%3};"
        : "+f"(c[0]), "+f"(c[1]), "+f"(c[2]), "+f"(c[3])
        : "r"(a0), "r"(a1), "r"(a2), "r"(a3), "r"(b0), "r"(b1));
}

// ---------------------------------------------------------------------------
// W prep with j-permutation: within each 16-k block, logical K row for
// fragment element k is  base + 4t + u  (t = lane&3), where
// k=2t ->u0, 2t+1 ->u1, 2t+8 ->u2, 2t+9 ->u3.  base = c*64 + s*16 (FI-indep).
// ---------------------------------------------------------------------------
__global__ void __launch_bounds__(256)
wfrag(const float* __restrict__ W, uint4* __restrict__ out) {
    const int c = blockIdx.x;
    for (int t = threadIdx.x; t < 1024; t += 256) {
        int s = t >> 8, f = (t >> 5) & 7, lane = t & 31;
        int n = f * 8 + (lane >> 2);
        int r = c * 64 + s * 16 + (lane & 3) * 4;
        float w0 = W[(r    ) * 128 + n], w1 = W[(r + 1) * 128 + n];
        float w2 = W[(r + 2) * 128 + n], w3 = W[(r + 3) * 128 + n];
        uint4 o;
        o.x = pack_hi(w0, w1);
        o.y = pack_hi(w2, w3);
        o.z = pack_lo(w0, w1);
        o.w = pack_lo(w2, w3);
        out[c * 1024 + t] = o;
    }
}

// ---------------------------------------------------------------------------
// Hidden layer via mma.sync (bf16 split). hout written [b][e][n], n<64.
// grid=512 (2 batches/CTA), block=256 (8 warps = 4m x 2n).
// hs padded to 80 words/row (conflict-free LDS.128 with the j-perm).
// ---------------------------------------------------------------------------
template<int FI>
__global__ void __launch_bounds__(256)
cin_mma(const float* __restrict__ x, const float* __restrict__ h,
        const uint4* __restrict__ Wf, const float* __restrict__ bias,
        float* __restrict__ hout)
{
    constexpr int NC = (32 * FI) / 64;   // 64-K chunks
    constexpr int OFF_XS = 256;
    constexpr int OFF_HS = OFF_XS + 128 * 33 * 4;   // 17152
    constexpr int OFF_B  = OFF_HS + 128 * 80 * 4;   // 58112

    extern __shared__ char smem[];
    float* bias_s = (float*)smem;
    float* xs = (float*)(smem + OFF_XS);   // [128][33]
    float* hs = (float*)(smem + OFF_HS);   // [128][80], cols 0..FI-1 valid
    const uint32_t Bsm = smem_u32(smem) + OFF_B;   // 2 x 16KB

    const int tid  = threadIdx.x;
    const int lane = tid & 31;
    const int wid  = tid >> 5;
    const int wm   = wid & 3, wn = wid >> 2;
    const int tq   = lane & 3;
    const int q2   = tq * 2;
    const int b0   = blockIdx.x * 2;

    if (tid < 64) bias_s[tid] = bias[tid];
    for (int idx = tid; idx < 4096; idx += 256) {
        int i = idx >> 7, mr = idx & 127;
        xs[mr * 33 + i] = x[((b0 + (mr >> 6)) * 32 + i) * 64 + (mr & 63)];
    }
    if (FI == 64) {
        // h in [b][e][j]: float4 coalesced, conflict-free STS.128
#pragma unroll
        for (int r = 0; r < 8; ++r) {
            int idx = tid + r * 256;
            int row = idx >> 4, c4 = idx & 15;
            float4 v = *(const float4*)&h[((b0 + (row >> 6)) * 64 + (row & 63)) * 64 + c4 * 4];
            *(float4*)&hs[row * 80 + c4 * 4] = v;
        }
    } else {
        // h = x in [b][i][e]: transposed scalar fill (one-time cost)
#pragma unroll
        for (int r = 0; r < 16; ++r) {
            int idx = tid + r * 256;
            int j = idx >> 7, mr = idx & 127;
            hs[mr * 80 + j] = h[((b0 + (mr >> 6)) * 32 + j) * 64 + (mr & 63)];
        }
    }

    // prefetch B chunks 0,1
#pragma unroll
    for (int pc = 0; pc < 2; ++pc) {
#pragma unroll
        for (int r = 0; r < 4; ++r) {
            uint32_t dst = Bsm + pc * 16384u + (uint32_t)(tid + r * 256) * 16u;
            const uint4* src = Wf + pc * 1024 + tid + r * 256;
            asm volatile("cp.async.cg.shared.global [%0], [%1], 16;"
                         :: "r"(dst), "l"(src));
        }
        asm volatile("cp.async.commit_group;");
    }

    float acc[2][4][4];
#pragma unroll
    for (int mf = 0; mf < 2; ++mf)
#pragma unroll
        for (int nf = 0; nf < 4; ++nf)
#pragma unroll
            for (int r = 0; r < 4; ++r) acc[mf][nf][r] = 0.f;

    const int ra_base = wm * 32 + (lane >> 2);

    for (int c = 0; c < NC; ++c) {
        asm volatile("cp.async.wait_group 1;" ::: "memory");
        __syncthreads();
        const uint32_t Bb = Bsm + (uint32_t)(c & 1) * 16384u;

        // hoist x values for this chunk
        float xreg[2][2][2];
#pragma unroll
        for (int mf = 0; mf < 2; ++mf) {
            const int ra = ra_base + mf * 16, rb = ra + 8;
            if (FI == 64) {
                xreg[mf][0][0] = xs[ra * 33 + c];
                xreg[mf][1][0] = xs[rb * 33 + c];
                xreg[mf][0][1] = xreg[mf][0][0];
                xreg[mf][1][1] = xreg[mf][1][0];
            } else {
                xreg[mf][0][0] = xs[ra * 33 + 2 * c];
                xreg[mf][1][0] = xs[rb * 33 + 2 * c];
                xreg[mf][0][1] = xs[ra * 33 + 2 * c + 1];
                xreg[mf][1][1] = xs[rb * 33 + 2 * c + 1];
            }
        }

#pragma unroll
        for (int s = 0; s < 4; ++s) {
            uint4 Bf[4];
#pragma unroll
            for (int nf = 0; nf < 4; ++nf) {
                uint32_t addr = Bb + (uint32_t)(((s * 8) + wn * 4 + nf) * 32 + lane) * 16u;
                asm volatile("ld.shared.v4.u32 {%0,%1,%2,%3}, [%4];"
                             : "=r"(Bf[nf].x), "=r"(Bf[nf].y),
                               "=r"(Bf[nf].z), "=r"(Bf[nf].w)
                             : "r"(addr));
            }
            const int jcol = ((FI == 64) ? s * 16 : (s & 1) * 16) + 4 * tq;
            const int isub = (FI == 64) ? 0 : (s >> 1);

#pragma unroll
            for (int mf = 0; mf < 2; ++mf) {
                const int ra = ra_base + mf * 16, rb = ra + 8;
                float4 ha = *(const float4*)&hs[ra * 80 + jcol];
                float4 hb = *(const float4*)&hs[rb * 80 + jcol];
                float xa = xreg[mf][0][isub], xb = xreg[mf][1][isub];
                float pa0 = xa * ha.x, pa1 = xa * ha.y, pa2 = xa * ha.z, pa3 = xa * ha.w;
                float pb0 = xb * hb.x, pb1 = xb * hb.y, pb2 = xb * hb.z, pb3 = xb * hb.w;
                uint32_t ah0 = pack_hi(pa0, pa1), ah1 = pack_hi(pb0, pb1);
                uint32_t ah2 = pack_hi(pa2, pa3), ah3 = pack_hi(pb2, pb3);
                uint32_t al0 = pack_lo(pa0, pa1), al1 = pack_lo(pb0, pb1);
                uint32_t al2 = pack_lo(pa2, pa3), al3 = pack_lo(pb2, pb3);
#pragma unroll
                for (int nf = 0; nf < 4; ++nf) {
                    mma16816(acc[mf][nf], ah0, ah1, ah2, ah3, Bf[nf].x, Bf[nf].y);
                    mma16816(acc[mf][nf], ah0, ah1, ah2, ah3, Bf[nf].z, Bf[nf].w);
                    mma16816(acc[mf][nf], al0, al1, al2, al3, Bf[nf].x, Bf[nf].y);
                }
            }
        }
        __syncthreads();
        if (c + 2 < NC) {
#pragma unroll
            for (int r = 0; r < 4; ++r) {
                uint32_t dst = Bsm + (uint32_t)(c & 1) * 16384u
                             + (uint32_t)(tid + r * 256) * 16u;
                const uint4* src = Wf + (c + 2) * 1024 + tid + r * 256;
                asm volatile("cp.async.cg.shared.global [%0], [%1], 16;"
                             :: "r"(dst), "l"(src));
            }
        }
        asm volatile("cp.async.commit_group;");
    }

    // epilogue: hout[b][e][n] = acc + bias
#pragma unroll
    for (int mf = 0; mf < 2; ++mf) {
        const int ra = ra_base + mf * 16;
        const int gb = b0 + (ra >> 6);
        const int e  = ra & 63;
        float* p0 = hout + ((size_t)gb * 64 + e) * 64;
        float* p8 = hout + ((size_t)gb * 64 + e + 8) * 64;
#pragma unroll
        for (int nf = 0; nf < 4; ++nf) {
            const int n = wn * 32 + nf * 8 + q2;
            float bv0 = bias_s[n], bv1 = bias_s[n + 1];
            float2 v0 = make_float2(acc[mf][nf][0] + bv0, acc[mf][nf][1] + bv1);
            float2 v8 = make_float2(acc[mf][nf][2] + bv0, acc[mf][nf][3] + bv1);
            *(float2*)&p0[n] = v0;
            *(float2*)&p8[n] = v8;
        }
    }
}

// ---------------------------------------------------------------------------
// S kernel: S[b][i*FI+j] = sum_e x[b,i,e]*h[b,j,e].  grid=1024, block=256.
// h layout: FI==32 -> [b][i][e] (x itself); FI==64 -> [b][e][j].
// ---------------------------------------------------------------------------
template<int FI>
__global__ void __launch_bounds__(256)
skern(const float* __restrict__ x, const float* __restrict__ h,
      float* __restrict__ S)
{
    constexpr int FAN = 32 * FI;
    __shared__ float xs[32 * 65];
    __shared__ float hs[FI * 65];
    const int b = blockIdx.x, tid = threadIdx.x;

    for (int idx = tid; idx < 2048; idx += 256) {
        int i = idx >> 6, e = idx & 63;
        xs[i * 65 + e] = x[(b * 32 + i) * 64 + e];
    }
    if (FI == 32) {
        for (int idx = tid; idx < 2048; idx += 256) {
            int j = idx >> 6, e = idx & 63;
            hs[j * 65 + e] = h[(b * 32 + j) * 64 + e];
        }
    } else {
        for (int idx = tid; idx < 4096; idx += 256) {
            int j = idx & 63, e = idx >> 6;
            hs[j * 65 + e] = h[(b * 64 + e) * 64 + j];
        }
    }
    __syncthreads();

    constexpr int DJ = FI / 16;          // 4 (FI=64) or 2 (FI=32)
    const int i0 = (tid >> 4) * 2;
    const int j0 = (tid & 15) * DJ;

    float acc[2][DJ];
#pragma unroll
    for (int di = 0; di < 2; ++di)
#pragma unroll
        for (int dj = 0; dj < DJ; ++dj) acc[di][dj] = 0.f;

#pragma unroll 4
    for (int e = 0; e < 64; ++e) {
        float x0 = xs[i0 * 65 + e];
        float x1 = xs[(i0 + 1) * 65 + e];
#pragma unroll
        for (int dj = 0; dj < DJ; ++dj) {
            float hv = hs[(j0 + dj) * 65 + e];
            acc[0][dj] += x0 * hv;
            acc[1][dj] += x1 * hv;
        }
    }
#pragma unroll
    for (int di = 0; di < 2; ++di)
#pragma unroll
        for (int dj = 0; dj < DJ; ++dj)
            S[(size_t)b * FAN + (i0 + di) * FI + (j0 + dj)] = acc[di][dj];
}

// ---------------------------------------------------------------------------
// Direct GEMM, deterministic k-split: part[z][b][outoff+n] = S[b, kslice].W.
// grid (8, KOUT/32, 8), block 256. BM=128, BN=32, BK=64.
// ---------------------------------------------------------------------------
template<int FAN>
__global__ void __launch_bounds__(256)
dgemm(const float* __restrict__ S, const float* __restrict__ W,
      float* __restrict__ part, int koff, int outoff)
{
    constexpr int KSL = FAN / 8;
    __shared__ float Sm[128 * 68];
    __shared__ float Wt[64 * 33];
    const int tid = threadIdx.x;
    const int m0 = blockIdx.x * 128, n0 = blockIdx.y * 32;
    const int k0 = blockIdx.z * KSL;
    const int ty = tid >> 3, tx = tid & 7;

    float acc[4][4];
#pragma unroll
    for (int r = 0; r < 4; ++r)
#pragma unroll
        for (int cn = 0; cn < 4; ++cn) acc[r][cn] = 0.f;

    for (int kc = 0; kc < KSL; kc += 64) {
        __syncthreads();
#pragma unroll
        for (int r = 0; r < 8; ++r) {
            int idx = tid + r * 256;
            int m = idx >> 4, kq = idx & 15;
            *(float4*)&Sm[m * 68 + kq * 4] =
                *(const float4*)&S[(size_t)(m0 + m) * FAN + k0 + kc + kq * 4];
        }
#pragma unroll
        for (int r = 0; r < 8; ++r) {
            int idx = tid + r * 256;
            int kk = idx >> 5, n = idx & 31;
            Wt[kk * 33 + n] = W[(size_t)(k0 + kc + kk) * 128 + koff + n0 + n];
        }
        __syncthreads();
#pragma unroll 4
        for (int k = 0; k < 64; ++k) {
            float a[4], bb[4];
#pragma unroll
            for (int r = 0; r < 4; ++r) a[r] = Sm[(ty * 4 + r) * 68 + k];
#pragma unroll
            for (int cn = 0; cn < 4; ++cn) bb[cn] = Wt[k * 33 + tx * 4 + cn];
#pragma unroll
            for (int r = 0; r < 4; ++r)
#pragma unroll
                for (int cn = 0; cn < 4; ++cn) acc[r][cn] += a[r] * bb[cn];
        }
    }

    float* pb = part + ((size_t)blockIdx.z * B_SZ) * 256;
#pragma unroll
    for (int r = 0; r < 4; ++r)
#pragma unroll
        for (int cn = 0; cn < 4; ++cn)
            pb[(size_t)(m0 + ty * 4 + r) * 256 + outoff + n0 + tx * 4 + cn] = acc[r][cn];
}

// ---------------------------------------------------------------------------
__global__ void __launch_bounds__(256)
reduce_out(const float* __restrict__ part, const float* __restrict__ b0,
           const float* __restrict__ b1, const float* __restrict__ b2,
           float* __restrict__ out)
{
    const int b = blockIdx.x, c = threadIdx.x;
    float v = (c < 64) ? b0[64 + c] : (c < 128) ? b1[c] : b2[c - 128];
    float s = 64.0f * v;
#pragma unroll
    for (int z = 0; z < 8; ++z)
        s += part[((size_t)z * B_SZ + b) * 256 + c];
    out[b * 256 + c] = s;
}

// ---------------------------------------------------------------------------
extern "C" void kernel_launch(void* const* d_in, const int* in_sizes, int n_in,
                              void* d_out, int out_size)
{
    const float* x  = (const float*)d_in[0];
    const float* W0 = (const float*)d_in[1];
    const float* b0 = (const float*)d_in[2];
    const float* W1 = (const float*)d_in[3];
    const float* b1 = (const float*)d_in[4];
    const float* W2 = (const float*)d_in[5];
    const float* b2 = (const float*)d_in[6];
    float* out = (float*)d_out;

    float *h1p, *h2p, *s0p, *s1p, *s2p, *pp;
    uint4 *wf0, *wf1;
    cudaGetSymbolAddress((void**)&h1p, g_h1);
    cudaGetSymbolAddress((void**)&h2p, g_h2);
    cudaGetSymbolAddress((void**)&wf0, g_Wf0);
    cudaGetSymbolAddress((void**)&wf1, g_Wf1);
    cudaGetSymbolAddress((void**)&s0p, g_S0);
    cudaGetSymbolAddress((void**)&s1p, g_S1);
    cudaGetSymbolAddress((void**)&s2p, g_S2);
    cudaGetSymbolAddress((void**)&pp,  g_part);

    const int smM = 256 + 128 * 33 * 4 + 128 * 80 * 4 + 32768;   // 90880
    cudaFuncSetAttribute(cin_mma<32>, cudaFuncAttributeMaxDynamicSharedMemorySize, smM);
    cudaFuncSetAttribute(cin_mma<64>, cudaFuncAttributeMaxDynamicSharedMemorySize, smM);

    wfrag<<<16, 256>>>(W0, wf0);
    wfrag<<<32, 256>>>(W1, wf1);

    cin_mma<32><<<512, 256, smM>>>(x, x,   wf0, b0, h1p);
    cin_mma<64><<<512, 256, smM>>>(x, h1p, wf1, b1, h2p);

    skern<32><<<B_SZ, 256>>>(x, x,   s0p);
    skern<64><<<B_SZ, 256>>>(x, h1p, s1p);
    skern<64><<<B_SZ, 256>>>(x, h2p, s2p);

    dgemm<1024><<<dim3(8, 2, 8), 256>>>(s0p, W0, pp, 64, 0);
    dgemm<2048><<<dim3(8, 2, 8), 256>>>(s1p, W1, pp, 64, 64);
    dgemm<2048><<<dim3(8, 4, 8), 256>>>(s2p, W2, pp, 0, 128);

    reduce_out<<<B_SZ, 256>>>(pp, b0, b1, b2, out);
}

// round 6
// speedup vs baseline: 2.7461x; 1.0018x over previous
#include <cuda_runtime.h>
#include <cuda_bf16.h>
#include <cstdint>

#define B_SZ 1024

// hidden activations, [b][e][j] layout (e-major for coalesced float4 fills)
__device__ float g_h1[B_SZ * 64 * 64];
__device__ float g_h2[B_SZ * 64 * 64];
// W fragment-linear: per 64-K chunk: [s(4)][nfrag(8)][lane(32)] uint4{hi01,hi23',lo01,lo23'}
__device__ __align__(16) uint4 g_Wf0[16 * 1024];
__device__ __align__(16) uint4 g_Wf1[32 * 1024];
// S matrices (direct path): S[b][i*FI+j]
__device__ float g_S0[B_SZ * 1024];
__device__ float g_S1[B_SZ * 2048];
__device__ float g_S2[B_SZ * 2048];
// k-split partials: [z(8)][b][256 cols]
__device__ float g_part[8 * B_SZ * 256];

__device__ __forceinline__ uint32_t smem_u32(const void* p) {
    uint32_t a;
    asm("{ .reg .u64 t; cvta.to.shared.u64 t, %1; cvt.u32.u64 %0, t; }" : "=r"(a) : "l"(p));
    return a;
}
__device__ __forceinline__ uint32_t pack_hi(float a, float b) {
    return __byte_perm(__float_as_uint(a), __float_as_uint(b), 0x7632);
}
__device__ __forceinline__ uint32_t pack_lo(float a, float b) {
    float la = a - __uint_as_float(__float_as_uint(a) & 0xFFFF0000u);
    float lb = b - __uint_as_float(__float_as_uint(b) & 0xFFFF0000u);
    uint32_t r;
    asm("cvt.rn.bf16x2.f32 %0, %1, %2;" : "=r"(r) : "f"(lb), "f"(la));
    return r;
}
__device__ __forceinline__ void mma16816(float* c, const uint32_t* a,
                                         uint32_t b0, uint32_t b1) {
    asm volatile(
        "mma.sync.aligned.m16n8k16.row.col.f32.bf16.bf16.f32 "
        "{%0,%1,%2,%3}, {%4,%5,%6,%7}, {%8,%9}, {%0,%1,%2,%3};"
        : "+f"(c[0]), "+f"(c[1]), "+f"(c[2]), "+f"(c[3])
        : "r"(a[0]), "r"(a[1]), "r"(a[2]), "r"(a[3]), "r"(b0), "r"(b1));
}

// ---------------------------------------------------------------------------
// W prep with j-permutation (fragment element u at lane t maps K row 4t+u).
// ---------------------------------------------------------------------------
__global__ void __launch_bounds__(256)
wfrag(const float* __restrict__ W, uint4* __restrict__ out) {
    const int c = blockIdx.x;
    for (int t = threadIdx.x; t < 1024; t += 256) {
        int s = t >> 8, f = (t >> 5) & 7, lane = t & 31;
        int n = f * 8 + (lane >> 2);
        int r = c * 64 + s * 16 + (lane & 3) * 4;
        float w0 = W[(r    ) * 128 + n], w1 = W[(r + 1) * 128 + n];
        float w2 = W[(r + 2) * 128 + n], w3 = W[(r + 3) * 128 + n];
        uint4 o;
        o.x = pack_hi(w0, w1);
        o.y = pack_hi(w2, w3);
        o.z = pack_lo(w0, w1);
        o.w = pack_lo(w2, w3);
        out[c * 1024 + t] = o;
    }
}

// ---------------------------------------------------------------------------
// Hidden layer via mma.sync (bf16 split), term-major MMA scheduling.
// hout written [b][e][n], n<64. grid=512, block=256 (8 warps = 4m x 2n).
// ---------------------------------------------------------------------------
template<int FI>
__global__ void __launch_bounds__(256)
cin_mma(const float* __restrict__ x, const float* __restrict__ h,
        const uint4* __restrict__ Wf, const float* __restrict__ bias,
        float* __restrict__ hout)
{
    constexpr int NC = (32 * FI) / 64;   // 64-K chunks
    constexpr int OFF_XS = 256;
    constexpr int OFF_HS = OFF_XS + 128 * 33 * 4;   // 17152
    constexpr int OFF_B  = OFF_HS + 128 * 80 * 4;   // 58112

    extern __shared__ char smem[];
    float* bias_s = (float*)smem;
    float* xs = (float*)(smem + OFF_XS);   // [128][33]
    float* hs = (float*)(smem + OFF_HS);   // [128][80]
    const uint32_t Bsm = smem_u32(smem) + OFF_B;   // 2 x 16KB

    const int tid  = threadIdx.x;
    const int lane = tid & 31;
    const int wid  = tid >> 5;
    const int wm   = wid & 3, wn = wid >> 2;
    const int tq   = lane & 3;
    const int q2   = tq * 2;
    const int b0   = blockIdx.x * 2;

    if (tid < 64) bias_s[tid] = bias[tid];
    for (int idx = tid; idx < 4096; idx += 256) {
        int i = idx >> 7, mr = idx & 127;
        xs[mr * 33 + i] = x[((b0 + (mr >> 6)) * 32 + i) * 64 + (mr & 63)];
    }
    if (FI == 64) {
#pragma unroll
        for (int r = 0; r < 8; ++r) {
            int idx = tid + r * 256;
            int row = idx >> 4, c4 = idx & 15;
            float4 v = *(const float4*)&h[((b0 + (row >> 6)) * 64 + (row & 63)) * 64 + c4 * 4];
            *(float4*)&hs[row * 80 + c4 * 4] = v;
        }
    } else {
#pragma unroll
        for (int r = 0; r < 16; ++r) {
            int idx = tid + r * 256;
            int j = idx >> 7, mr = idx & 127;
            hs[mr * 80 + j] = h[((b0 + (mr >> 6)) * 32 + j) * 64 + (mr & 63)];
        }
    }

    // prefetch B chunks 0,1
#pragma unroll
    for (int pc = 0; pc < 2; ++pc) {
#pragma unroll
        for (int r = 0; r < 4; ++r) {
            uint32_t dst = Bsm + pc * 16384u + (uint32_t)(tid + r * 256) * 16u;
            const uint4* src = Wf + pc * 1024 + tid + r * 256;
            asm volatile("cp.async.cg.shared.global [%0], [%1], 16;"
                         :: "r"(dst), "l"(src));
        }
        asm volatile("cp.async.commit_group;");
    }

    float acc[2][4][4];
#pragma unroll
    for (int mf = 0; mf < 2; ++mf)
#pragma unroll
        for (int nf = 0; nf < 4; ++nf)
#pragma unroll
            for (int r = 0; r < 4; ++r) acc[mf][nf][r] = 0.f;

    const int ra_base = wm * 32 + (lane >> 2);

    for (int c = 0; c < NC; ++c) {
        asm volatile("cp.async.wait_group 1;" ::: "memory");
        __syncthreads();
        const uint32_t Bb = Bsm + (uint32_t)(c & 1) * 16384u;

        float xreg[2][2][2];
#pragma unroll
        for (int mf = 0; mf < 2; ++mf) {
            const int ra = ra_base + mf * 16, rb = ra + 8;
            if (FI == 64) {
                xreg[mf][0][0] = xs[ra * 33 + c];
                xreg[mf][1][0] = xs[rb * 33 + c];
                xreg[mf][0][1] = xreg[mf][0][0];
                xreg[mf][1][1] = xreg[mf][1][0];
            } else {
                xreg[mf][0][0] = xs[ra * 33 + 2 * c];
                xreg[mf][1][0] = xs[rb * 33 + 2 * c];
                xreg[mf][0][1] = xs[ra * 33 + 2 * c + 1];
                xreg[mf][1][1] = xs[rb * 33 + 2 * c + 1];
            }
        }

#pragma unroll
        for (int s = 0; s < 4; ++s) {
            uint4 Bf[4];
#pragma unroll
            for (int nf = 0; nf < 4; ++nf) {
                uint32_t addr = Bb + (uint32_t)(((s * 8) + wn * 4 + nf) * 32 + lane) * 16u;
                asm volatile("ld.shared.v4.u32 {%0,%1,%2,%3}, [%4];"
                             : "=r"(Bf[nf].x), "=r"(Bf[nf].y),
                               "=r"(Bf[nf].z), "=r"(Bf[nf].w)
                             : "r"(addr));
            }
            const int jcol = ((FI == 64) ? s * 16 : (s & 1) * 16) + 4 * tq;
            const int isub = (FI == 64) ? 0 : (s >> 1);

            // ---- A-gen for BOTH mf blocks first (fills ah/al registers) ----
            uint32_t ah[2][4], al[2][4];
#pragma unroll
            for (int mf = 0; mf < 2; ++mf) {
                const int ra = ra_base + mf * 16, rb = ra + 8;
                float4 ha = *(const float4*)&hs[ra * 80 + jcol];
                float4 hb = *(const float4*)&hs[rb * 80 + jcol];
                float xa = xreg[mf][0][isub], xb = xreg[mf][1][isub];
                float pa0 = xa * ha.x, pa1 = xa * ha.y, pa2 = xa * ha.z, pa3 = xa * ha.w;
                float pb0 = xb * hb.x, pb1 = xb * hb.y, pb2 = xb * hb.z, pb3 = xb * hb.w;
                ah[mf][0] = pack_hi(pa0, pa1); ah[mf][1] = pack_hi(pb0, pb1);
                ah[mf][2] = pack_hi(pa2, pa3); ah[mf][3] = pack_hi(pb2, pb3);
                al[mf][0] = pack_lo(pa0, pa1); al[mf][1] = pack_lo(pb0, pb1);
                al[mf][2] = pack_lo(pa2, pa3); al[mf][3] = pack_lo(pb2, pb3);
            }

            // ---- term-major MMA issue: dependents 8 apart ----
#pragma unroll
            for (int mf = 0; mf < 2; ++mf)
#pragma unroll
                for (int nf = 0; nf < 4; ++nf)
                    mma16816(acc[mf][nf], ah[mf], Bf[nf].x, Bf[nf].y);
#pragma unroll
            for (int mf = 0; mf < 2; ++mf)
#pragma unroll
                for (int nf = 0; nf < 4; ++nf)
                    mma16816(acc[mf][nf], ah[mf], Bf[nf].z, Bf[nf].w);
#pragma unroll
            for (int mf = 0; mf < 2; ++mf)
#pragma unroll
                for (int nf = 0; nf < 4; ++nf)
                    mma16816(acc[mf][nf], al[mf], Bf[nf].x, Bf[nf].y);
        }
        __syncthreads();
        if (c + 2 < NC) {
#pragma unroll
            for (int r = 0; r < 4; ++r) {
                uint32_t dst = Bsm + (uint32_t)(c & 1) * 16384u
                             + (uint32_t)(tid + r * 256) * 16u;
                const uint4* src = Wf + (c + 2) * 1024 + tid + r * 256;
                asm volatile("cp.async.cg.shared.global [%0], [%1], 16;"
                             :: "r"(dst), "l"(src));
            }
        }
        asm volatile("cp.async.commit_group;");
    }

    // epilogue: hout[b][e][n] = acc + bias
#pragma unroll
    for (int mf = 0; mf < 2; ++mf) {
        const int ra = ra_base + mf * 16;
        const int gb = b0 + (ra >> 6);
        const int e  = ra & 63;
        float* p0 = hout + ((size_t)gb * 64 + e) * 64;
        float* p8 = hout + ((size_t)gb * 64 + e + 8) * 64;
#pragma unroll
        for (int nf = 0; nf < 4; ++nf) {
            const int n = wn * 32 + nf * 8 + q2;
            float bv0 = bias_s[n], bv1 = bias_s[n + 1];
            float2 v0 = make_float2(acc[mf][nf][0] + bv0, acc[mf][nf][1] + bv1);
            float2 v8 = make_float2(acc[mf][nf][2] + bv0, acc[mf][nf][3] + bv1);
            *(float2*)&p0[n] = v0;
            *(float2*)&p8[n] = v8;
        }
    }
}

// ---------------------------------------------------------------------------
// S kernel: S[b][i*FI+j] = sum_e x[b,i,e]*h[b,j,e].  grid=1024, block=256.
// ---------------------------------------------------------------------------
template<int FI>
__global__ void __launch_bounds__(256)
skern(const float* __restrict__ x, const float* __restrict__ h,
      float* __restrict__ S)
{
    constexpr int FAN = 32 * FI;
    __shared__ float xs[32 * 65];
    __shared__ float hs[FI * 65];
    const int b = blockIdx.x, tid = threadIdx.x;

    for (int idx = tid; idx < 2048; idx += 256) {
        int i = idx >> 6, e = idx & 63;
        xs[i * 65 + e] = x[(b * 32 + i) * 64 + e];
    }
    if (FI == 32) {
        for (int idx = tid; idx < 2048; idx += 256) {
            int j = idx >> 6, e = idx & 63;
            hs[j * 65 + e] = h[(b * 32 + j) * 64 + e];
        }
    } else {
        for (int idx = tid; idx < 4096; idx += 256) {
            int j = idx & 63, e = idx >> 6;
            hs[j * 65 + e] = h[(b * 64 + e) * 64 + j];
        }
    }
    __syncthreads();

    constexpr int DJ = FI / 16;
    const int i0 = (tid >> 4) * 2;
    const int j0 = (tid & 15) * DJ;

    float acc[2][DJ];
#pragma unroll
    for (int di = 0; di < 2; ++di)
#pragma unroll
        for (int dj = 0; dj < DJ; ++dj) acc[di][dj] = 0.f;

#pragma unroll 4
    for (int e = 0; e < 64; ++e) {
        float x0 = xs[i0 * 65 + e];
        float x1 = xs[(i0 + 1) * 65 + e];
#pragma unroll
        for (int dj = 0; dj < DJ; ++dj) {
            float hv = hs[(j0 + dj) * 65 + e];
            acc[0][dj] += x0 * hv;
            acc[1][dj] += x1 * hv;
        }
    }
#pragma unroll
    for (int di = 0; di < 2; ++di)
#pragma unroll
        for (int dj = 0; dj < DJ; ++dj)
            S[(size_t)b * FAN + (i0 + di) * FI + (j0 + dj)] = acc[di][dj];
}

// ---------------------------------------------------------------------------
// Direct GEMM, deterministic k-split.
// ---------------------------------------------------------------------------
template<int FAN>
__global__ void __launch_bounds__(256)
dgemm(const float* __restrict__ S, const float* __restrict__ W,
      float* __restrict__ part, int koff, int outoff)
{
    constexpr int KSL = FAN / 8;
    __shared__ float Sm[128 * 68];
    __shared__ float Wt[64 * 33];
    const int tid = threadIdx.x;
    const int m0 = blockIdx.x * 128, n0 = blockIdx.y * 32;
    const int k0 = blockIdx.z * KSL;
    const int ty = tid >> 3, tx = tid & 7;

    float acc[4][4];
#pragma unroll
    for (int r = 0; r < 4; ++r)
#pragma unroll
        for (int cn = 0; cn < 4; ++cn) acc[r][cn] = 0.f;

    for (int kc = 0; kc < KSL; kc += 64) {
        __syncthreads();
#pragma unroll
        for (int r = 0; r < 8; ++r) {
            int idx = tid + r * 256;
            int m = idx >> 4, kq = idx & 15;
            *(float4*)&Sm[m * 68 + kq * 4] =
                *(const float4*)&S[(size_t)(m0 + m) * FAN + k0 + kc + kq * 4];
        }
#pragma unroll
        for (int r = 0; r < 8; ++r) {
            int idx = tid + r * 256;
            int kk = idx >> 5, n = idx & 31;
            Wt[kk * 33 + n] = W[(size_t)(k0 + kc + kk) * 128 + koff + n0 + n];
        }
        __syncthreads();
#pragma unroll 4
        for (int k = 0; k < 64; ++k) {
            float a[4], bb[4];
#pragma unroll
            for (int r = 0; r < 4; ++r) a[r] = Sm[(ty * 4 + r) * 68 + k];
#pragma unroll
            for (int cn = 0; cn < 4; ++cn) bb[cn] = Wt[k * 33 + tx * 4 + cn];
#pragma unroll
            for (int r = 0; r < 4; ++r)
#pragma unroll
                for (int cn = 0; cn < 4; ++cn) acc[r][cn] += a[r] * bb[cn];
        }
    }

    float* pb = part + ((size_t)blockIdx.z * B_SZ) * 256;
#pragma unroll
    for (int r = 0; r < 4; ++r)
#pragma unroll
        for (int cn = 0; cn < 4; ++cn)
            pb[(size_t)(m0 + ty * 4 + r) * 256 + outoff + n0 + tx * 4 + cn] = acc[r][cn];
}

// ---------------------------------------------------------------------------
__global__ void __launch_bounds__(256)
reduce_out(const float* __restrict__ part, const float* __restrict__ b0,
           const float* __restrict__ b1, const float* __restrict__ b2,
           float* __restrict__ out)
{
    const int b = blockIdx.x, c = threadIdx.x;
    float v = (c < 64) ? b0[64 + c] : (c < 128) ? b1[c] : b2[c - 128];
    float s = 64.0f * v;
#pragma unroll
    for (int z = 0; z < 8; ++z)
        s += part[((size_t)z * B_SZ + b) * 256 + c];
    out[b * 256 + c] = s;
}

// ---------------------------------------------------------------------------
extern "C" void kernel_launch(void* const* d_in, const int* in_sizes, int n_in,
                              void* d_out, int out_size)
{
    const float* x  = (const float*)d_in[0];
    const float* W0 = (const float*)d_in[1];
    const float* b0 = (const float*)d_in[2];
    const float* W1 = (const float*)d_in[3];
    const float* b1 = (const float*)d_in[4];
    const float* W2 = (const float*)d_in[5];
    const float* b2 = (const float*)d_in[6];
    float* out = (float*)d_out;

    float *h1p, *h2p, *s0p, *s1p, *s2p, *pp;
    uint4 *wf0, *wf1;
    cudaGetSymbolAddress((void**)&h1p, g_h1);
    cudaGetSymbolAddress((void**)&h2p, g_h2);
    cudaGetSymbolAddress((void**)&wf0, g_Wf0);
    cudaGetSymbolAddress((void**)&wf1, g_Wf1);
    cudaGetSymbolAddress((void**)&s0p, g_S0);
    cudaGetSymbolAddress((void**)&s1p, g_S1);
    cudaGetSymbolAddress((void**)&s2p, g_S2);
    cudaGetSymbolAddress((void**)&pp,  g_part);

    const int smM = 256 + 128 * 33 * 4 + 128 * 80 * 4 + 32768;   // 90880
    cudaFuncSetAttribute(cin_mma<32>, cudaFuncAttributeMaxDynamicSharedMemorySize, smM);
    cudaFuncSetAttribute(cin_mma<64>, cudaFuncAttributeMaxDynamicSharedMemorySize, smM);

    wfrag<<<16, 256>>>(W0, wf0);
    wfrag<<<32, 256>>>(W1, wf1);

    cin_mma<32><<<512, 256, smM>>>(x, x,   wf0, b0, h1p);
    cin_mma<64><<<512, 256, smM>>>(x, h1p, wf1, b1, h2p);

    skern<32><<<B_SZ, 256>>>(x, x,   s0p);
    skern<64><<<B_SZ, 256>>>(x, h1p, s1p);
    skern<64><<<B_SZ, 256>>>(x, h2p, s2p);

    dgemm<1024><<<dim3(8, 2, 8), 256>>>(s0p, W0, pp, 64, 0);
    dgemm<2048><<<dim3(8, 2, 8), 256>>>(s1p, W1, pp, 64, 64);
    dgemm<2048><<<dim3(8, 4, 8), 256>>>(s2p, W2, pp, 0, 128);

    reduce_out<<<B_SZ, 256>>>(pp, b0, b1, b2, out);
}